// round 8
// baseline (speedup 1.0000x reference)
#include <cuda_runtime.h>
#include <cstdint>

// Kohonen SOM pairwise L2 distance via tf32 mma.sync.m16n8k8.
//   out[b][n] = sqrt(max(||x_b||^2 + ||w_n||^2 - 2 x_b.w_n, 0))
// x [B=65536,32] f32, w [N=4900,32] f32, out [B,N] f32.
//
// R8 = R7 (128x128 tile, 4x2 warps, permuted B-fragment columns -> STG.128
// epilogue) plus:
//  (a) NORMS FUSED INTO THE MMA: a 5th k-step with A-frag [x2, 1, 0...] and
//      B-frag [1, w2, 0...] (built from tiny smem arrays via SEL, -2 folded
//      into the x tile at fill). Accumulators become squared distances;
//      epilogue is just max+sqrt+store (removes 128 FADD/FFMA/thread).
//  (b) K-PAIR PERMUTATION: physical k -> smem pos 8*ks + 2*qc + j, so each
//      fragment's (qc, qc+4) k-pair is one LDS.64 (48 loads vs 96 LDS.32).

#define BM 128
#define BN 128
#define KD 32

#define SWZ(row) ((((row) ^ ((row) >> 1)) & 7) << 2)
#define SIDX(row, col) (((row) << 5) + (((col) ^ SWZ(row)) & 31))

__device__ __forceinline__ float to_tf32(float a) {
    float r;
    asm("cvt.rna.tf32.f32 %0, %1;" : "=f"(r) : "f"(a));
    return r;
}

__device__ __forceinline__ float fsqrt_approx(float a) {
    float r;
    asm("sqrt.approx.f32 %0, %1;" : "=f"(r) : "f"(a));
    return r;
}

__device__ __forceinline__ void mma_tf32(float* c, const float* a, const float* b) {
    asm volatile(
        "mma.sync.aligned.m16n8k8.row.col.f32.tf32.tf32.f32 "
        "{%0,%1,%2,%3}, {%4,%5,%6,%7}, {%8,%9}, {%0,%1,%2,%3};"
        : "+f"(c[0]), "+f"(c[1]), "+f"(c[2]), "+f"(c[3])
        : "r"(__float_as_uint(a[0])), "r"(__float_as_uint(a[1])),
          "r"(__float_as_uint(a[2])), "r"(__float_as_uint(a[3])),
          "r"(__float_as_uint(b[0])), "r"(__float_as_uint(b[1])));
}

__global__ __launch_bounds__(256, 2)
void som_mma_kernel(const float* __restrict__ x,
                    const float* __restrict__ w,
                    float* __restrict__ out,
                    int B, int N) {
    __shared__ float As[BM * KD];     // 16 KB: -2*x, k-pair permuted, swizzled
    __shared__ float Bs[BN * KD];     // 16 KB: w, same layout
    __shared__ float x2s[BM];         // tf32-rounded norms
    __shared__ float w2s[BN];

    const int tid    = threadIdx.x;
    const int m_base = blockIdx.y * BM;
    const int n_base = blockIdx.x * BN;

    // ---- fill: threads 0..127 -> x rows (scaled by -2), 128..255 -> w rows ----
    // k-pair permutation: physical k = 8ks+4j+qc  -> pos = 8ks + 2qc + j
    if (tid < BM) {
        const float4* src = (const float4*)(x + (size_t)(m_base + tid) * KD);
        float nrm = 0.f;
        #pragma unroll
        for (int ks = 0; ks < 4; ++ks) {
            float4 a = src[2 * ks];       // k = 8ks..8ks+3  (j=0)
            float4 b = src[2 * ks + 1];   // k = 8ks+4..+7   (j=1)
            nrm = fmaf(a.x, a.x, nrm); nrm = fmaf(a.y, a.y, nrm);
            nrm = fmaf(a.z, a.z, nrm); nrm = fmaf(a.w, a.w, nrm);
            nrm = fmaf(b.x, b.x, nrm); nrm = fmaf(b.y, b.y, nrm);
            nrm = fmaf(b.z, b.z, nrm); nrm = fmaf(b.w, b.w, nrm);
            *(float2*)&As[SIDX(tid, 8 * ks + 0)] = make_float2(-2.f * a.x, -2.f * b.x);
            *(float2*)&As[SIDX(tid, 8 * ks + 2)] = make_float2(-2.f * a.y, -2.f * b.y);
            *(float2*)&As[SIDX(tid, 8 * ks + 4)] = make_float2(-2.f * a.z, -2.f * b.z);
            *(float2*)&As[SIDX(tid, 8 * ks + 6)] = make_float2(-2.f * a.w, -2.f * b.w);
        }
        x2s[tid] = to_tf32(nrm);
    } else {
        const int row = tid - BM;
        const int gn  = n_base + row;
        float nrm = 0.f;
        if (gn < N) {
            const float4* src = (const float4*)(w + (size_t)gn * KD);
            #pragma unroll
            for (int ks = 0; ks < 4; ++ks) {
                float4 a = src[2 * ks];
                float4 b = src[2 * ks + 1];
                nrm = fmaf(a.x, a.x, nrm); nrm = fmaf(a.y, a.y, nrm);
                nrm = fmaf(a.z, a.z, nrm); nrm = fmaf(a.w, a.w, nrm);
                nrm = fmaf(b.x, b.x, nrm); nrm = fmaf(b.y, b.y, nrm);
                nrm = fmaf(b.z, b.z, nrm); nrm = fmaf(b.w, b.w, nrm);
                *(float2*)&Bs[SIDX(row, 8 * ks + 0)] = make_float2(a.x, b.x);
                *(float2*)&Bs[SIDX(row, 8 * ks + 2)] = make_float2(a.y, b.y);
                *(float2*)&Bs[SIDX(row, 8 * ks + 4)] = make_float2(a.z, b.z);
                *(float2*)&Bs[SIDX(row, 8 * ks + 6)] = make_float2(a.w, b.w);
            }
        } else {
            float2 z = make_float2(0.f, 0.f);
            #pragma unroll
            for (int p = 0; p < 16; ++p) *(float2*)&Bs[SIDX(row, 2 * p)] = z;
        }
        w2s[row] = to_tf32(nrm);
    }
    __syncthreads();

    // ---- warp-tiled mainloop ----
    const int lane   = tid & 31;
    const int wid    = tid >> 5;
    const int warp_m = (wid & 3) * 32;   // 4 warps along M
    const int warp_n = (wid >> 2) * 64;  // 2 warps along N
    const int qr     = lane >> 2;        // 0..7
    const int qc     = lane & 3;         // 0..3

    // permuted B-fragment row (R7): col owned = warp_n + qc*4 + i*16 {+0..3}
    const int pq = (qr >> 1) * 4 + (qr & 1);

    float acc[2][8][4];
    #pragma unroll
    for (int i = 0; i < 2; ++i)
        #pragma unroll
        for (int j = 0; j < 8; ++j)
            #pragma unroll
            for (int v = 0; v < 4; ++v) acc[i][j][v] = 0.f;

    #pragma unroll
    for (int ks = 0; ks < 4; ++ks) {
        const int pp = 8 * ks + 2 * qc;   // LDS.64 pos: (k=8ks+qc, k=8ks+qc+4)

        float af[2][4];
        #pragma unroll
        for (int tm = 0; tm < 2; ++tm) {
            const int r = warp_m + tm * 16 + qr;
            float2 p0 = *(const float2*)&As[SIDX(r,     pp)];
            float2 p1 = *(const float2*)&As[SIDX(r + 8, pp)];
            af[tm][0] = p0.x; af[tm][1] = p1.x;   // k = 8ks+qc
            af[tm][2] = p0.y; af[tm][3] = p1.y;   // k = 8ks+qc+4
        }

        float bf[8][2];
        #pragma unroll
        for (int tn = 0; tn < 8; ++tn) {
            const int c = warp_n + pq + (tn >> 1) * 16 + (tn & 1) * 2;
            float2 q = *(const float2*)&Bs[SIDX(c, pp)];
            bf[tn][0] = q.x; bf[tn][1] = q.y;
        }

        #pragma unroll
        for (int tm = 0; tm < 2; ++tm)
            #pragma unroll
            for (int tn = 0; tn < 8; ++tn)
                mma_tf32(acc[tm][tn], af[tm], bf[tn]);
    }

    // ---- 5th k-step: fold norms.  A2 = [x2, 1, 0..], B2 = [1, w2, 0..] ----
    {
        float a5[2][4];
        #pragma unroll
        for (int tm = 0; tm < 2; ++tm) {
            const int r = warp_m + tm * 16 + qr;
            const float x2a = x2s[r];
            const float x2b = x2s[r + 8];
            a5[tm][0] = (qc == 0) ? x2a : ((qc == 1) ? 1.f : 0.f);
            a5[tm][1] = (qc == 0) ? x2b : ((qc == 1) ? 1.f : 0.f);
            a5[tm][2] = 0.f;
            a5[tm][3] = 0.f;
        }
        #pragma unroll
        for (int tn = 0; tn < 8; ++tn) {
            const int c = warp_n + pq + (tn >> 1) * 16 + (tn & 1) * 2;
            const float w2c = w2s[c];
            float b5[2];
            b5[0] = (qc == 0) ? 1.f : ((qc == 1) ? w2c : 0.f);
            b5[1] = 0.f;
            #pragma unroll
            for (int tm = 0; tm < 2; ++tm)
                mma_tf32(acc[tm][tn], a5[tm], b5);
        }
    }

    // ---- epilogue: acc is already squared distance -> max, sqrt, STG.128 ----
    #pragma unroll
    for (int tm = 0; tm < 2; ++tm) {
        const int r_lo = warp_m + tm * 16 + qr;
        const size_t off_lo = (size_t)(m_base + r_lo) * N;
        const size_t off_hi = off_lo + (size_t)8 * N;

        #pragma unroll
        for (int i = 0; i < 4; ++i) {
            const int c  = warp_n + qc * 4 + i * 16;
            const int gn = n_base + c;
            if (gn < N) {                         // N%4==0 -> gn+3 valid
                const float* a0 = acc[tm][2 * i];      // cols c, c+1
                const float* a1 = acc[tm][2 * i + 1];  // cols c+2, c+3

                float4 lo, hi;
                lo.x = fsqrt_approx(fmaxf(a0[0], 0.f));
                lo.y = fsqrt_approx(fmaxf(a0[1], 0.f));
                lo.z = fsqrt_approx(fmaxf(a1[0], 0.f));
                lo.w = fsqrt_approx(fmaxf(a1[1], 0.f));
                hi.x = fsqrt_approx(fmaxf(a0[2], 0.f));
                hi.y = fsqrt_approx(fmaxf(a0[3], 0.f));
                hi.z = fsqrt_approx(fmaxf(a1[2], 0.f));
                hi.w = fsqrt_approx(fmaxf(a1[3], 0.f));

                __stcs((float4*)(out + off_lo + gn), lo);
                __stcs((float4*)(out + off_hi + gn), hi);
            }
        }
    }
}

extern "C" void kernel_launch(void* const* d_in, const int* in_sizes, int n_in,
                              void* d_out, int out_size) {
    const float* x = (const float*)d_in[0];
    const float* w = (const float*)d_in[1];
    float* out     = (float*)d_out;

    int B = in_sizes[0] / KD;   // 65536
    int N = in_sizes[1] / KD;   // 4900

    dim3 grid((N + BN - 1) / BN, (B + BM - 1) / BM);
    som_mma_kernel<<<grid, 256>>>(x, w, out, B, N);
}

// round 9
// speedup vs baseline: 1.2453x; 1.2453x over previous
#include <cuda_runtime.h>
#include <cstdint>

// Kohonen SOM pairwise L2 distance via tf32 mma.sync.m16n8k8.
//   out[b][n] = sqrt(max(||x_b||^2 + ||w_n||^2 - 2 x_b.w_n, 0))
// x [B=65536,32] f32, w [N=4900,32] f32, out [B,N] f32.
//
// R9 = R7 dataflow (128x128 CTA tile, permuted B-fragment columns ->
// STG.128 epilogue, LDS.32 mainloop) but 512 threads/CTA: 16 warps, 4x4
// warp grid, 32x32 warp tile (acc 32 regs). __launch_bounds__(512,2)
// -> 2 CTAs/SM = 32 warps (~50% occ, double R7) at the same grid.
// Fill: each row split across 2 threads; half-row norms combined via smem.

#define BM 128
#define BN 128
#define KD 32

#define SWZ(row) ((((row) ^ ((row) >> 1)) & 7) << 2)
#define SIDX(row, col) (((row) << 5) + (((col) ^ SWZ(row)) & 31))

__device__ __forceinline__ float to_tf32(float a) {
    float r;
    asm("cvt.rna.tf32.f32 %0, %1;" : "=f"(r) : "f"(a));
    return r;
}

__device__ __forceinline__ float fsqrt_approx(float a) {
    float r;
    asm("sqrt.approx.f32 %0, %1;" : "=f"(r) : "f"(a));
    return r;
}

__device__ __forceinline__ void mma_tf32(float* c, const unsigned* a, const unsigned* b) {
    asm volatile(
        "mma.sync.aligned.m16n8k8.row.col.f32.tf32.tf32.f32 "
        "{%0,%1,%2,%3}, {%4,%5,%6,%7}, {%8,%9}, {%0,%1,%2,%3};"
        : "+f"(c[0]), "+f"(c[1]), "+f"(c[2]), "+f"(c[3])
        : "r"(a[0]), "r"(a[1]), "r"(a[2]), "r"(a[3]),
          "r"(b[0]), "r"(b[1]));
}

__global__ __launch_bounds__(512, 2)
void som_mma_kernel(const float* __restrict__ x,
                    const float* __restrict__ w,
                    float* __restrict__ out,
                    int B, int N) {
    __shared__ float As[BM * KD];     // 16 KB, swizzled tf32(x)
    __shared__ float Bs[BN * KD];     // 16 KB, swizzled tf32(w)
    __shared__ float p2[512];         // half-row norm partials
    __shared__ float x2s[BM];
    __shared__ float w2s[BN];

    const int tid    = threadIdx.x;
    const int m_base = blockIdx.y * BM;
    const int n_base = blockIdx.x * BN;

    // ---- fill: thread t -> row t>>1 (0..255), half t&1 (16 floats) ----
    {
        const int row  = tid >> 1;
        const int half = tid & 1;
        const int q0   = half * 4;            // float4 index base within row
        float nrm = 0.f;

        if (row < BM) {
            const float4* src = (const float4*)(x + (size_t)(m_base + row) * KD);
            #pragma unroll
            for (int q = 0; q < 4; ++q) {
                float4 v = src[q0 + q];
                nrm = fmaf(v.x, v.x, nrm); nrm = fmaf(v.y, v.y, nrm);
                nrm = fmaf(v.z, v.z, nrm); nrm = fmaf(v.w, v.w, nrm);
                float4 t = make_float4(to_tf32(v.x), to_tf32(v.y),
                                       to_tf32(v.z), to_tf32(v.w));
                *(float4*)&As[SIDX(row, (q0 + q) * 4)] = t;
            }
        } else {
            const int brow = row - BM;
            const int gn   = n_base + brow;
            if (gn < N) {
                const float4* src = (const float4*)(w + (size_t)gn * KD);
                #pragma unroll
                for (int q = 0; q < 4; ++q) {
                    float4 v = src[q0 + q];
                    nrm = fmaf(v.x, v.x, nrm); nrm = fmaf(v.y, v.y, nrm);
                    nrm = fmaf(v.z, v.z, nrm); nrm = fmaf(v.w, v.w, nrm);
                    float4 t = make_float4(to_tf32(v.x), to_tf32(v.y),
                                           to_tf32(v.z), to_tf32(v.w));
                    *(float4*)&Bs[SIDX(brow, (q0 + q) * 4)] = t;
                }
            } else {
                float4 z = make_float4(0.f, 0.f, 0.f, 0.f);
                #pragma unroll
                for (int q = 0; q < 4; ++q)
                    *(float4*)&Bs[SIDX(brow, (q0 + q) * 4)] = z;
            }
        }
        p2[tid] = nrm;
    }
    __syncthreads();

    if (tid < BM) {
        x2s[tid] = p2[2 * tid] + p2[2 * tid + 1];
    } else if (tid < BM + BN) {
        const int r = tid - BM;
        w2s[r] = p2[2 * tid] + p2[2 * tid + 1];
    }
    __syncthreads();

    // ---- 4x4 warp grid, 32x32 warp tile, permuted B-fragment columns ----
    const int lane   = tid & 31;
    const int wid    = tid >> 5;
    const int warp_m = (wid & 3) * 32;    // 4 warps along M
    const int warp_n = (wid >> 2) * 32;   // 4 warps along N
    const int qr     = lane >> 2;         // 0..7
    const int qc     = lane & 3;          // 0..3

    // permuted physical w-row for fragment tn, col-slot qr:
    //   warp_n + pq + (tn>>1)*16 + (tn&1)*2
    const int pq = (qr >> 1) * 4 + (qr & 1);

    float acc[2][4][4];
    #pragma unroll
    for (int i = 0; i < 2; ++i)
        #pragma unroll
        for (int j = 0; j < 4; ++j)
            #pragma unroll
            for (int v = 0; v < 4; ++v) acc[i][j][v] = 0.f;

    #pragma unroll
    for (int ks = 0; ks < 4; ++ks) {
        const int k0 = ks * 8;

        unsigned af[2][4];
        #pragma unroll
        for (int tm = 0; tm < 2; ++tm) {
            const int r = warp_m + tm * 16 + qr;
            af[tm][0] = __float_as_uint(As[SIDX(r,     k0 + qc    )]);
            af[tm][1] = __float_as_uint(As[SIDX(r + 8, k0 + qc    )]);
            af[tm][2] = __float_as_uint(As[SIDX(r,     k0 + qc + 4)]);
            af[tm][3] = __float_as_uint(As[SIDX(r + 8, k0 + qc + 4)]);
        }

        unsigned bf[4][2];
        #pragma unroll
        for (int tn = 0; tn < 4; ++tn) {
            const int c = warp_n + pq + (tn >> 1) * 16 + (tn & 1) * 2;
            bf[tn][0] = __float_as_uint(Bs[SIDX(c, k0 + qc    )]);
            bf[tn][1] = __float_as_uint(Bs[SIDX(c, k0 + qc + 4)]);
        }

        #pragma unroll
        for (int tm = 0; tm < 2; ++tm)
            #pragma unroll
            for (int tn = 0; tn < 4; ++tn)
                mma_tf32(acc[tm][tn], af[tm], bf[tn]);
    }

    // ---- epilogue: thread owns cols warp_n + qc*4 + i*16 + {0..3} ----
    #pragma unroll
    for (int tm = 0; tm < 2; ++tm) {
        const int r_lo = warp_m + tm * 16 + qr;
        const float x2_lo = x2s[r_lo];
        const float x2_hi = x2s[r_lo + 8];
        const size_t off_lo = (size_t)(m_base + r_lo) * N;
        const size_t off_hi = off_lo + (size_t)8 * N;

        #pragma unroll
        for (int i = 0; i < 2; ++i) {
            const int c  = warp_n + qc * 4 + i * 16;
            const int gn = n_base + c;
            if (gn < N) {                          // N%4==0 -> gn+3 valid
                const float4 w2v = *(const float4*)&w2s[c];
                const float* a0 = acc[tm][2 * i];      // cols c, c+1
                const float* a1 = acc[tm][2 * i + 1];  // cols c+2, c+3

                float4 lo, hi;
                lo.x = fsqrt_approx(fmaxf(fmaf(-2.f, a0[0], x2_lo + w2v.x), 0.f));
                lo.y = fsqrt_approx(fmaxf(fmaf(-2.f, a0[1], x2_lo + w2v.y), 0.f));
                lo.z = fsqrt_approx(fmaxf(fmaf(-2.f, a1[0], x2_lo + w2v.z), 0.f));
                lo.w = fsqrt_approx(fmaxf(fmaf(-2.f, a1[1], x2_lo + w2v.w), 0.f));
                hi.x = fsqrt_approx(fmaxf(fmaf(-2.f, a0[2], x2_hi + w2v.x), 0.f));
                hi.y = fsqrt_approx(fmaxf(fmaf(-2.f, a0[3], x2_hi + w2v.y), 0.f));
                hi.z = fsqrt_approx(fmaxf(fmaf(-2.f, a1[2], x2_hi + w2v.z), 0.f));
                hi.w = fsqrt_approx(fmaxf(fmaf(-2.f, a1[3], x2_hi + w2v.w), 0.f));

                __stcs((float4*)(out + off_lo + gn), lo);
                __stcs((float4*)(out + off_hi + gn), hi);
            }
        }
    }
}

extern "C" void kernel_launch(void* const* d_in, const int* in_sizes, int n_in,
                              void* d_out, int out_size) {
    const float* x = (const float*)d_in[0];
    const float* w = (const float*)d_in[1];
    float* out     = (float*)d_out;

    int B = in_sizes[0] / KD;   // 65536
    int N = in_sizes[1] / KD;   // 4900

    dim3 grid((N + BN - 1) / BN, (B + BM - 1) / BM);
    som_mma_kernel<<<grid, 512>>>(x, w, out, B, N);
}

// round 10
// speedup vs baseline: 1.2497x; 1.0035x over previous
#include <cuda_runtime.h>
#include <cstdint>

// Kohonen SOM pairwise L2 distance via tf32 mma.sync.m16n8k8.
//   out[b][n] = sqrt(max(||x_b||^2 + ||w_n||^2 - 2 x_b.w_n, 0))
// x [B=65536,32] f32, w [N=4900,32] f32, out [B,N] f32.
//
// R10 = R9 (128x128 CTA tile, 512 threads, 4x4 warp grid, 32x32 warp tile,
// permuted B-fragment columns -> STG.128 epilogue) with the XOR smem swizzle
// replaced by PADDED PITCH 36. (36r + col) % 32 == (4r + col) % 32 keeps all
// fragment loads and float4 fills bank-conflict-free, while letting ptxas
// fold all k-step offsets into LDS immediates (the XOR swizzle forced
// LOP3+IADD per load -> alu pipe 40% in R9; R3's pitch-36 ran alu 15%).

#define BM 128
#define BN 128
#define KD 32
#define SP 36     // padded pitch in floats

#define SIDX(row, col) ((row) * SP + (col))

__device__ __forceinline__ float to_tf32(float a) {
    float r;
    asm("cvt.rna.tf32.f32 %0, %1;" : "=f"(r) : "f"(a));
    return r;
}

__device__ __forceinline__ float fsqrt_approx(float a) {
    float r;
    asm("sqrt.approx.f32 %0, %1;" : "=f"(r) : "f"(a));
    return r;
}

__device__ __forceinline__ void mma_tf32(float* c, const unsigned* a, const unsigned* b) {
    asm volatile(
        "mma.sync.aligned.m16n8k8.row.col.f32.tf32.tf32.f32 "
        "{%0,%1,%2,%3}, {%4,%5,%6,%7}, {%8,%9}, {%0,%1,%2,%3};"
        : "+f"(c[0]), "+f"(c[1]), "+f"(c[2]), "+f"(c[3])
        : "r"(a[0]), "r"(a[1]), "r"(a[2]), "r"(a[3]),
          "r"(b[0]), "r"(b[1]));
}

__global__ __launch_bounds__(512, 2)
void som_mma_kernel(const float* __restrict__ x,
                    const float* __restrict__ w,
                    float* __restrict__ out,
                    int B, int N) {
    __shared__ float As[BM * SP];     // 18 KB, pitch-36 tf32(x)
    __shared__ float Bs[BN * SP];     // 18 KB, pitch-36 tf32(w)
    __shared__ float p2[512];         // half-row norm partials
    __shared__ float x2s[BM];
    __shared__ float w2s[BN];

    const int tid    = threadIdx.x;
    const int m_base = blockIdx.y * BM;
    const int n_base = blockIdx.x * BN;

    // ---- fill: thread t -> row t>>1 (0..255), half t&1 (16 floats) ----
    {
        const int row  = tid >> 1;
        const int half = tid & 1;
        const int q0   = half * 4;            // float4 index base within row
        float nrm = 0.f;

        if (row < BM) {
            const float4* src = (const float4*)(x + (size_t)(m_base + row) * KD);
            #pragma unroll
            for (int q = 0; q < 4; ++q) {
                float4 v = src[q0 + q];
                nrm = fmaf(v.x, v.x, nrm); nrm = fmaf(v.y, v.y, nrm);
                nrm = fmaf(v.z, v.z, nrm); nrm = fmaf(v.w, v.w, nrm);
                float4 t = make_float4(to_tf32(v.x), to_tf32(v.y),
                                       to_tf32(v.z), to_tf32(v.w));
                *(float4*)&As[SIDX(row, (q0 + q) * 4)] = t;
            }
        } else {
            const int brow = row - BM;
            const int gn   = n_base + brow;
            if (gn < N) {
                const float4* src = (const float4*)(w + (size_t)gn * KD);
                #pragma unroll
                for (int q = 0; q < 4; ++q) {
                    float4 v = src[q0 + q];
                    nrm = fmaf(v.x, v.x, nrm); nrm = fmaf(v.y, v.y, nrm);
                    nrm = fmaf(v.z, v.z, nrm); nrm = fmaf(v.w, v.w, nrm);
                    float4 t = make_float4(to_tf32(v.x), to_tf32(v.y),
                                           to_tf32(v.z), to_tf32(v.w));
                    *(float4*)&Bs[SIDX(brow, (q0 + q) * 4)] = t;
                }
            } else {
                float4 z = make_float4(0.f, 0.f, 0.f, 0.f);
                #pragma unroll
                for (int q = 0; q < 4; ++q)
                    *(float4*)&Bs[SIDX(brow, (q0 + q) * 4)] = z;
            }
        }
        p2[tid] = nrm;
    }
    __syncthreads();

    if (tid < BM) {
        x2s[tid] = p2[2 * tid] + p2[2 * tid + 1];
    } else if (tid < BM + BN) {
        const int r = tid - BM;
        w2s[r] = p2[2 * tid] + p2[2 * tid + 1];
    }
    __syncthreads();

    // ---- 4x4 warp grid, 32x32 warp tile, permuted B-fragment columns ----
    const int lane   = tid & 31;
    const int wid    = tid >> 5;
    const int warp_m = (wid & 3) * 32;    // 4 warps along M
    const int warp_n = (wid >> 2) * 32;   // 4 warps along N
    const int qr     = lane >> 2;         // 0..7
    const int qc     = lane & 3;          // 0..3

    // permuted physical w-row for fragment tn, col-slot qr:
    //   warp_n + pq + (tn>>1)*16 + (tn&1)*2
    const int pq = (qr >> 1) * 4 + (qr & 1);

    // hoisted row bases (one IMAD each; all k offsets become immediates)
    const float* a_row0 = &As[SIDX(warp_m + qr, qc)];
    const float* b_row0 = &Bs[SIDX(warp_n + pq, qc)];

    float acc[2][4][4];
    #pragma unroll
    for (int i = 0; i < 2; ++i)
        #pragma unroll
        for (int j = 0; j < 4; ++j)
            #pragma unroll
            for (int v = 0; v < 4; ++v) acc[i][j][v] = 0.f;

    #pragma unroll
    for (int ks = 0; ks < 4; ++ks) {
        const int k0 = ks * 8;

        unsigned af[2][4];
        #pragma unroll
        for (int tm = 0; tm < 2; ++tm) {
            const float* r0 = a_row0 + tm * 16 * SP;
            af[tm][0] = __float_as_uint(r0[k0]);
            af[tm][1] = __float_as_uint(r0[8 * SP + k0]);
            af[tm][2] = __float_as_uint(r0[k0 + 4]);
            af[tm][3] = __float_as_uint(r0[8 * SP + k0 + 4]);
        }

        unsigned bf[4][2];
        #pragma unroll
        for (int tn = 0; tn < 4; ++tn) {
            const float* c0 = b_row0 + ((tn >> 1) * 16 + (tn & 1) * 2) * SP;
            bf[tn][0] = __float_as_uint(c0[k0]);
            bf[tn][1] = __float_as_uint(c0[k0 + 4]);
        }

        #pragma unroll
        for (int tm = 0; tm < 2; ++tm)
            #pragma unroll
            for (int tn = 0; tn < 4; ++tn)
                mma_tf32(acc[tm][tn], af[tm], bf[tn]);
    }

    // ---- epilogue: thread owns cols warp_n + qc*4 + i*16 + {0..3} ----
    #pragma unroll
    for (int tm = 0; tm < 2; ++tm) {
        const int r_lo = warp_m + tm * 16 + qr;
        const float x2_lo = x2s[r_lo];
        const float x2_hi = x2s[r_lo + 8];
        const size_t off_lo = (size_t)(m_base + r_lo) * N;
        const size_t off_hi = off_lo + (size_t)8 * N;

        #pragma unroll
        for (int i = 0; i < 2; ++i) {
            const int c  = warp_n + qc * 4 + i * 16;
            const int gn = n_base + c;
            if (gn < N) {                          // N%4==0 -> gn+3 valid
                const float4 w2v = *(const float4*)&w2s[c];
                const float* a0 = acc[tm][2 * i];      // cols c, c+1
                const float* a1 = acc[tm][2 * i + 1];  // cols c+2, c+3

                float4 lo, hi;
                lo.x = fsqrt_approx(fmaxf(fmaf(-2.f, a0[0], x2_lo + w2v.x), 0.f));
                lo.y = fsqrt_approx(fmaxf(fmaf(-2.f, a0[1], x2_lo + w2v.y), 0.f));
                lo.z = fsqrt_approx(fmaxf(fmaf(-2.f, a1[0], x2_lo + w2v.z), 0.f));
                lo.w = fsqrt_approx(fmaxf(fmaf(-2.f, a1[1], x2_lo + w2v.w), 0.f));
                hi.x = fsqrt_approx(fmaxf(fmaf(-2.f, a0[2], x2_hi + w2v.x), 0.f));
                hi.y = fsqrt_approx(fmaxf(fmaf(-2.f, a0[3], x2_hi + w2v.y), 0.f));
                hi.z = fsqrt_approx(fmaxf(fmaf(-2.f, a1[2], x2_hi + w2v.z), 0.f));
                hi.w = fsqrt_approx(fmaxf(fmaf(-2.f, a1[3], x2_hi + w2v.w), 0.f));

                __stcs((float4*)(out + off_lo + gn), lo);
                __stcs((float4*)(out + off_hi + gn), hi);
            }
        }
    }
}

extern "C" void kernel_launch(void* const* d_in, const int* in_sizes, int n_in,
                              void* d_out, int out_size) {
    const float* x = (const float*)d_in[0];
    const float* w = (const float*)d_in[1];
    float* out     = (float*)d_out;

    int B = in_sizes[0] / KD;   // 65536
    int N = in_sizes[1] / KD;   // 4900

    dim3 grid((N + BN - 1) / BN, (B + BM - 1) / BM);
    som_mma_kernel<<<grid, 512>>>(x, w, out, B, N);
}